// round 16
// baseline (speedup 1.0000x reference)
#include <cuda_runtime.h>

#define D_FEAT 64
#define MAX_NODES 100000
#define NODES_PER_WARP 4

// Scratch (static __device__ array -- no allocation).
__device__ int g_row_ptr[MAX_NODES + 1];

// Build row_ptr from the sorted target index: row_ptr[v] = first edge e with
// tgt[e] >= v. Boundary ranges are disjoint across e -> race-free writes.
__global__ __launch_bounds__(256) void build_row_ptr_kernel(
    const int* __restrict__ tgt, int n_edges, int n_nodes)
{
    const int e = blockIdx.x * blockDim.x + threadIdx.x;
    if (e >= n_edges) return;
    const int cur  = __ldg(tgt + e);
    const int prev = (e == 0) ? -1 : __ldg(tgt + e - 1);
    for (int v = prev + 1; v <= cur; ++v) g_row_ptr[v] = e;
    if (e == n_edges - 1) {
        for (int v = cur + 1; v <= n_nodes; ++v) g_row_ptr[v] = n_edges;
    }
}

// One warp serves FOUR consecutive nodes (whole warp per edge, f32 direct).
// Rationale: with 1 node/warp, a block's 4 warp slots idle until its
// slowest warp (E[max of 4 Poisson(16)] ~ 22 vs mean 16 => ~27% waste).
// 4 nodes/warp shrinks the per-warp work spread ~2x (sum of 4 Poissons),
// lifting block-retire efficiency ~73% -> ~89%. Inner loop is R15's:
// f32 row = 256B = 32 lanes x float2; per edge 1 SHFL(s) + 1 IADD +
// 1 LDG.64 + 1 SHFL(w) + 2 FFMA; unroll 4 -> 4 edges in flight.
__global__ __launch_bounds__(128) void mp_gather_kernel(
    const float* __restrict__ x,    // [n_nodes, 64]
    const float* __restrict__ ev,   // [n_edges]
    const int*   __restrict__ src,  // [n_edges]
    float*       __restrict__ out,  // [n_nodes, 64]
    int n_nodes)
{
    const int warp = (blockIdx.x * blockDim.x + threadIdx.x) >> 5;
    const int v0   = warp * NODES_PER_WARP;
    if (v0 >= n_nodes) return;
    const int lane  = threadIdx.x & 31;
    const int lane8 = lane << 3;          // byte offset of this lane's float2

    const char* __restrict__ xb = (const char*)x;   // row s at byte s*256
    float2* __restrict__ of2 = (float2*)out;

    #pragma unroll 1
    for (int i = 0; i < NODES_PER_WARP; ++i) {
        const int node = v0 + i;
        if (node >= n_nodes) break;

        const int start = __ldg(&g_row_ptr[node]);
        const int end   = __ldg(&g_row_ptr[node + 1]);

        float ax = 0.f, ay = 0.f;

        for (int base = start; base < end; base += 32) {
            const int cnt = min(32, end - base);
            // Cooperative metadata load: lane l owns edge base+l.
            // Source index pre-shifted to a byte row offset (s * 256).
            int   s_l = 0;
            float w_l = 0.f;
            if (lane < cnt) {
                s_l = __ldg(src + base + lane) << 8;
                w_l = __ldg(ev  + base + lane);
            }

            int k = 0;
            // Main path: 4 edges in flight (4 x LDG.64).
            for (; k + 4 <= cnt; k += 4) {
                const int o0 = __shfl_sync(0xffffffffu, s_l, k + 0) + lane8;
                const int o1 = __shfl_sync(0xffffffffu, s_l, k + 1) + lane8;
                const int o2 = __shfl_sync(0xffffffffu, s_l, k + 2) + lane8;
                const int o3 = __shfl_sync(0xffffffffu, s_l, k + 3) + lane8;
                const float2 f0 = __ldg((const float2*)(xb + o0));
                const float2 f1 = __ldg((const float2*)(xb + o1));
                const float2 f2 = __ldg((const float2*)(xb + o2));
                const float2 f3 = __ldg((const float2*)(xb + o3));
                const float w0 = __shfl_sync(0xffffffffu, w_l, k + 0);
                const float w1 = __shfl_sync(0xffffffffu, w_l, k + 1);
                const float w2 = __shfl_sync(0xffffffffu, w_l, k + 2);
                const float w3 = __shfl_sync(0xffffffffu, w_l, k + 3);
                ax = fmaf(w0, f0.x, ax); ay = fmaf(w0, f0.y, ay);
                ax = fmaf(w1, f1.x, ax); ay = fmaf(w1, f1.y, ay);
                ax = fmaf(w2, f2.x, ax); ay = fmaf(w2, f2.y, ay);
                ax = fmaf(w3, f3.x, ax); ay = fmaf(w3, f3.y, ay);
            }
            // Tail: one edge at a time (<= 3).
            for (; k < cnt; ++k) {
                const int   o = __shfl_sync(0xffffffffu, s_l, k) + lane8;
                const float w = __shfl_sync(0xffffffffu, w_l, k);
                const float2 f = __ldg((const float2*)(xb + o));
                ax = fmaf(w, f.x, ax);
                ay = fmaf(w, f.y, ay);
            }
        }

        // Every lane stores its own feature pair: 32 x 8B = 256B coalesced.
        of2[(size_t)node * 32 + lane] = make_float2(ax, ay);
    }
}

extern "C" void kernel_launch(void* const* d_in, const int* in_sizes, int n_in,
                              void* d_out, int out_size) {
    const float* x   = (const float*)d_in[0];
    const float* ev  = (const float*)d_in[1];
    const int*   tgt = (const int*)d_in[2];
    const int*   src = (const int*)d_in[3];
    float* out = (float*)d_out;

    const int n_edges = in_sizes[1];
    const int n_nodes = out_size / D_FEAT;

    build_row_ptr_kernel<<<(n_edges + 255) / 256, 256>>>(tgt, n_edges, n_nodes);

    const int threads = 128;
    const int warps_needed = (n_nodes + NODES_PER_WARP - 1) / NODES_PER_WARP;
    const int blocks = (warps_needed * 32 + threads - 1) / threads;
    mp_gather_kernel<<<blocks, threads>>>(x, ev, src, out, n_nodes);
}